// round 3
// baseline (speedup 1.0000x reference)
#include <cuda_runtime.h>

// NNSystem_mech: tiny neuro-endocrine ODE RHS. Single-warp, latency-optimized.
// Input order (metadata):
// 0 t, 1 y, 2 aiw, 3 aib, 4 apw1, 5 apb1, 6 apw2, 7 apb2,
// 8 anw1, 9 anb1, 10 anw2, 11 anb2, 12 arw, 13 arb,
// 14 ciw, 15 cib, 16 cpw1, 17 cpb1, 18 cpw2, 19 cpb2,
// 20 cnw1, 21 cnb1, 22 cnw2, 23 cnb2, 24 crw, 25 crb, 26 K_i, 27 n_hill

struct Params {
    const float* y;
    const float* aiw; const float* aib;
    const float* apw1; const float* apb1; const float* apw2; const float* apb2;
    const float* anw1; const float* anb1; const float* anw2; const float* anb2;
    const float* arw; const float* arb;
    const float* ciw; const float* cib;
    const float* cpw1; const float* cpb1; const float* cpw2; const float* cpb2;
    const float* cnw1; const float* cnb1; const float* cnw2; const float* cnb2;
    const float* crw; const float* crb;
    const float* K_i; const float* n_hill;
};

// Fast softplus: max(x,0) + log(1 + exp(-|x|)) with MUFU-based exp/log.
// For |x| large, exp(-|x|) underflows toward 0 and log(1+e)->0; absolute error
// vs log1p is < e itself, negligible against the max(x,0) term.
__device__ __forceinline__ float softplus_fast(float x) {
    float e = __expf(-fabsf(x));
    return fmaxf(x, 0.0f) + __logf(1.0f + e);
}

// pow for strictly positive base (y1 ~ U(0,1), K_i = 1.5)
__device__ __forceinline__ float pow_pos(float b, float n) {
    return exp2f(n * __log2f(b));
}

__global__ void nnsys_kernel(Params p, float* out) {
    const int lane = threadIdx.x;          // 0..31
    const int seg  = lane >> 3;            // group 0..3: a_pos, a_neg, c_pos, c_neg
    const int u0   = lane & 7;             // hidden unit 0..7 (units 8,9 on u0<2)

    // ---- front-load everything independent ----
    const float y0 = p.y[0];
    const float y1 = p.y[1];

    // tail-stage params: load early in every lane so latency overlaps compute
    const float arw0 = p.arw[0], arw1 = p.arw[1], arb = p.arb[0];
    const float crw0 = p.crw[0], crw1 = p.crw[1], crb = p.crb[0];
    const float Ki   = p.K_i[0], nh   = p.n_hill[0];

    // per-group front-end params + hidden-unit weights
    float iw, ib, yin, b2;
    const float *w1p, *b1p, *w2p;
    if (seg == 0) {
        iw = p.aiw[0]; ib = p.aib[0]; yin = y0; b2 = p.apb2[0];
        w1p = p.apw1; b1p = p.apb1; w2p = p.apw2;
    } else if (seg == 1) {
        iw = p.aiw[1]; ib = p.aib[1]; yin = y0; b2 = p.anb2[0];
        w1p = p.anw1; b1p = p.anb1; w2p = p.anw2;
    } else if (seg == 2) {
        iw = p.ciw[0]; ib = p.cib[0]; yin = y1; b2 = p.cpb2[0];
        w1p = p.cpw1; b1p = p.cpb1; w2p = p.cpw2;
    } else {
        iw = p.ciw[1]; ib = p.cib[1]; yin = y1; b2 = p.cnb2[0];
        w1p = p.cnw1; b1p = p.cnb1; w2p = p.cnw2;
    }

    // issue hidden-unit loads (independent of the softplus below)
    const float w1a = w1p[u0], b1a = b1p[u0], w2a = w2p[u0];
    float w1b = 0.f, b1b = 0.f, w2b = 0.f;
    const bool second = (u0 < 2);
    if (second) { w1b = w1p[8 + u0]; b1b = b1p[8 + u0]; w2b = w2p[8 + u0]; }

    // ---- compute ----
    const float x = softplus_fast(fmaf(iw, yin, ib));

    float local = w2a * softplus_fast(fmaf(w1a, x, b1a));
    if (second) local += w2b * softplus_fast(fmaf(w1b, x, b1b));
    if (u0 == 0) local += b2;  // fold output bias into the segment sum

    // segment (width-8) butterfly reduce
    local += __shfl_xor_sync(0xffffffffu, local, 1, 8);
    local += __shfl_xor_sync(0xffffffffu, local, 2, 8);
    local += __shfl_xor_sync(0xffffffffu, local, 4, 8);

    // gather the four group sums into every lane (only lane 0 uses them)
    const float a_pos = __shfl_sync(0xffffffffu, local, 0);
    const float a_neg = __shfl_sync(0xffffffffu, local, 8);
    const float c_pos = __shfl_sync(0xffffffffu, local, 16);
    const float c_neg = __shfl_sync(0xffffffffu, local, 24);

    if (lane == 0) {
        const float Kn   = pow_pos(Ki, nh);
        const float hill = Kn / (Kn + pow_pos(y1, nh));

        const float av0 = softplus_fast(hill * a_pos);
        const float av1 = softplus_fast(a_neg);
        const float cv0 = softplus_fast(y0 * c_pos);
        const float cv1 = softplus_fast(c_neg);

        float2 r;
        r.x = fmaf(arw0, av0, fmaf(arw1, av1, arb));
        r.y = fmaf(crw0, cv0, fmaf(crw1, cv1, crb));
        *reinterpret_cast<float2*>(out) = r;
    }
}

extern "C" void kernel_launch(void* const* d_in, const int* in_sizes, int n_in,
                              void* d_out, int out_size) {
    (void)in_sizes; (void)n_in; (void)out_size;
    Params p;
    p.y    = (const float*)d_in[1];
    p.aiw  = (const float*)d_in[2];  p.aib  = (const float*)d_in[3];
    p.apw1 = (const float*)d_in[4];  p.apb1 = (const float*)d_in[5];
    p.apw2 = (const float*)d_in[6];  p.apb2 = (const float*)d_in[7];
    p.anw1 = (const float*)d_in[8];  p.anb1 = (const float*)d_in[9];
    p.anw2 = (const float*)d_in[10]; p.anb2 = (const float*)d_in[11];
    p.arw  = (const float*)d_in[12]; p.arb  = (const float*)d_in[13];
    p.ciw  = (const float*)d_in[14]; p.cib  = (const float*)d_in[15];
    p.cpw1 = (const float*)d_in[16]; p.cpb1 = (const float*)d_in[17];
    p.cpw2 = (const float*)d_in[18]; p.cpb2 = (const float*)d_in[19];
    p.cnw1 = (const float*)d_in[20]; p.cnb1 = (const float*)d_in[21];
    p.cnw2 = (const float*)d_in[22]; p.cnb2 = (const float*)d_in[23];
    p.crw  = (const float*)d_in[24]; p.crb  = (const float*)d_in[25];
    p.K_i  = (const float*)d_in[26]; p.n_hill = (const float*)d_in[27];

    nnsys_kernel<<<1, 32>>>(p, (float*)d_out);
}